// round 4
// baseline (speedup 1.0000x reference)
#include <cuda_runtime.h>
#include <math.h>
#include <stdint.h>

#define BATCH 4
#define SEQ   1024
#define DIM   512
#define NH    8
#define DHD   64
#define R2    2047   // 2*SEQ-1

// ---------------- scratch (static device memory; no allocs) ----------------
__device__ float g_q[BATCH*SEQ*DIM];
__device__ float g_k[BATCH*SEQ*DIM];
__device__ float g_v[BATCH*SEQ*DIM];
__device__ float g_pe[R2*DIM];
__device__ float g_E[R2*DIM];
__device__ float g_att[BATCH*SEQ*DIM];

// ---------------- relative sinusoidal PE (all-float) ----------------------
__global__ void pe_kernel(float* __restrict__ pe) {
    int i = blockIdx.x;           // 0..2046
    int j = threadIdx.x;          // 0..255
    float pos  = (float)(SEQ - 1 - i);
    float invf = expf(-(float)j * 0.03597789207803197f);   // ln(1e4)/256
    float ang  = pos * invf;
    float s, c;
    sincosf(ang, &s, &c);
    pe[(size_t)i*DIM + 2*j]     = s;
    pe[(size_t)i*DIM + 2*j + 1] = c;
}

// ---------------- 3xTF32 tensor-core GEMM: C = A @ W^T + bias -------------
// 128x128 tile, K-chunk 16, 8 warps (2x4), warp tile 64x32 = 4x4 m16n8k8.
// hi/lo tf32 split stored interleaved in smem -> float2 fragment loads.

__device__ __forceinline__ uint32_t f2tf(float x) {
    uint32_t r;
    asm("cvt.rna.tf32.f32 %0, %1;" : "=r"(r) : "f"(x));
    return r;
}

__device__ __forceinline__ void mma_tf32(float c[4], uint32_t a0, uint32_t a1,
                                         uint32_t a2, uint32_t a3,
                                         uint32_t b0, uint32_t b1) {
    asm volatile(
        "mma.sync.aligned.m16n8k8.row.col.f32.tf32.tf32.f32 "
        "{%0,%1,%2,%3}, {%4,%5,%6,%7}, {%8,%9}, {%0,%1,%2,%3};"
        : "+f"(c[0]), "+f"(c[1]), "+f"(c[2]), "+f"(c[3])
        : "r"(a0), "r"(a1), "r"(a2), "r"(a3), "r"(b0), "r"(b1));
}

#define SP 260   // smem pitch in floats: 2*128 + 4

__device__ __forceinline__
void gemm_tf32_body(const float* __restrict__ A, const float* __restrict__ W,
                    const float* __restrict__ bias, float* __restrict__ C, int M) {
    __shared__ float sA[16][SP];
    __shared__ float sW[16][SP];

    const int tid  = threadIdx.x;
    const int lane = tid & 31;
    const int warp = tid >> 5;
    const int r    = lane >> 2;       // 0..7
    const int cg   = lane & 3;        // 0..3
    const int m0w  = (warp >> 2) * 64;
    const int n0w  = (warp & 3) * 32;
    const int m0   = blockIdx.y * 128;
    const int n0   = blockIdx.x * 128;
    const int lr   = tid >> 2;        // 0..63
    const int lc   = (tid & 3) * 4;   // 0,4,8,12

    float acc[4][4][4];
    #pragma unroll
    for (int mt = 0; mt < 4; mt++)
        #pragma unroll
        for (int nt = 0; nt < 4; nt++)
            #pragma unroll
            for (int e = 0; e < 4; e++) acc[mt][nt][e] = 0.f;

    for (int k0 = 0; k0 < DIM; k0 += 16) {
        // ---- gmem -> smem with hi/lo split ----
        #pragma unroll
        for (int half = 0; half < 2; half++) {
            int row = lr + half * 64;
            int m   = m0 + row;
            float4 va = make_float4(0.f, 0.f, 0.f, 0.f);
            if (m < M) va = *(const float4*)(A + (size_t)m*DIM + k0 + lc);
            float av[4] = {va.x, va.y, va.z, va.w};
            #pragma unroll
            for (int c = 0; c < 4; c++) {
                uint32_t hi = f2tf(av[c]);
                float hif = __uint_as_float(hi);
                uint32_t lo = f2tf(av[c] - hif);
                sA[lc+c][2*row]   = hif;
                sA[lc+c][2*row+1] = __uint_as_float(lo);
            }
            float4 vb = *(const float4*)(W + (size_t)(n0+row)*DIM + k0 + lc);
            float bv[4] = {vb.x, vb.y, vb.z, vb.w};
            #pragma unroll
            for (int c = 0; c < 4; c++) {
                uint32_t hi = f2tf(bv[c]);
                float hif = __uint_as_float(hi);
                uint32_t lo = f2tf(bv[c] - hif);
                sW[lc+c][2*row]   = hif;
                sW[lc+c][2*row+1] = __uint_as_float(lo);
            }
        }
        __syncthreads();

        #pragma unroll
        for (int ks = 0; ks < 16; ks += 8) {
            // A fragments for 4 m-subtiles (hi+lo via float2)
            uint32_t ah[4][4], al[4][4];
            #pragma unroll
            for (int mt = 0; mt < 4; mt++) {
                int base = m0w + mt*16 + r;
                float2 v0 = *(float2*)&sA[ks+cg][2*base];        // a0
                float2 v1 = *(float2*)&sA[ks+cg][2*(base+8)];    // a1
                float2 v2 = *(float2*)&sA[ks+cg+4][2*base];      // a2
                float2 v3 = *(float2*)&sA[ks+cg+4][2*(base+8)];  // a3
                ah[mt][0] = __float_as_uint(v0.x); al[mt][0] = __float_as_uint(v0.y);
                ah[mt][1] = __float_as_uint(v1.x); al[mt][1] = __float_as_uint(v1.y);
                ah[mt][2] = __float_as_uint(v2.x); al[mt][2] = __float_as_uint(v2.y);
                ah[mt][3] = __float_as_uint(v3.x); al[mt][3] = __float_as_uint(v3.y);
            }
            #pragma unroll
            for (int nt = 0; nt < 4; nt++) {
                int ncol = n0w + nt*8 + r;
                float2 w0 = *(float2*)&sW[ks+cg][2*ncol];        // b0
                float2 w1 = *(float2*)&sW[ks+cg+4][2*ncol];      // b1
                uint32_t bh0 = __float_as_uint(w0.x), bl0 = __float_as_uint(w0.y);
                uint32_t bh1 = __float_as_uint(w1.x), bl1 = __float_as_uint(w1.y);
                #pragma unroll
                for (int mt = 0; mt < 4; mt++) {
                    mma_tf32(acc[mt][nt], ah[mt][0], ah[mt][1], ah[mt][2], ah[mt][3], bh0, bh1);
                    mma_tf32(acc[mt][nt], ah[mt][0], ah[mt][1], ah[mt][2], ah[mt][3], bl0, bl1);
                    mma_tf32(acc[mt][nt], al[mt][0], al[mt][1], al[mt][2], al[mt][3], bh0, bh1);
                }
            }
        }
        __syncthreads();
    }

    // ---- epilogue: bias + store ----
    #pragma unroll
    for (int mt = 0; mt < 4; mt++) {
        int m = m0 + m0w + mt*16 + r;
        #pragma unroll
        for (int nt = 0; nt < 4; nt++) {
            int n = n0 + n0w + nt*8 + 2*cg;
            float2 bb = *(const float2*)(bias + n);
            if (m < M) {
                float2 o0 = make_float2(acc[mt][nt][0] + bb.x, acc[mt][nt][1] + bb.y);
                *(float2*)(C + (size_t)m*DIM + n) = o0;
            }
            if (m + 8 < M) {
                float2 o1 = make_float2(acc[mt][nt][2] + bb.x, acc[mt][nt][3] + bb.y);
                *(float2*)(C + (size_t)(m+8)*DIM + n) = o1;
            }
        }
    }
}

// Fused Q/K/V/E projections: z selects operand set. Grid (4, 32, 4);
// z==3 (E, M=2047 -> 16 y-tiles) masks y>=16.
__global__ __launch_bounds__(256)
void proj_fused(const float* __restrict__ q_in, const float* __restrict__ k_in,
                const float* __restrict__ v_in, const float* __restrict__ pe_in,
                const float* __restrict__ Wq, const float* __restrict__ bq,
                const float* __restrict__ Wk, const float* __restrict__ bk,
                const float* __restrict__ Wv, const float* __restrict__ bv,
                const float* __restrict__ Wp, const float* __restrict__ bp,
                float* __restrict__ oq, float* __restrict__ ok,
                float* __restrict__ ov, float* __restrict__ oE) {
    int z = blockIdx.z;
    const float *A, *W, *b; float* C; int M;
    if (z == 0)      { A = q_in;  W = Wq; b = bq; C = oq; M = BATCH*SEQ; }
    else if (z == 1) { A = k_in;  W = Wk; b = bk; C = ok; M = BATCH*SEQ; }
    else if (z == 2) { A = v_in;  W = Wv; b = bv; C = ov; M = BATCH*SEQ; }
    else             { A = pe_in; W = Wp; b = bp; C = oE; M = R2;
                       if (blockIdx.y >= 16) return; }
    gemm_tf32_body(A, W, b, C, M);
}

__global__ __launch_bounds__(256)
void gemm_tf32(const float* __restrict__ A, const float* __restrict__ W,
               const float* __restrict__ bias, float* __restrict__ C, int M) {
    gemm_tf32_body(A, W, bias, C, M);
}

// ---------------- fused rel-pos flash attention (unchanged SIMT) ----------
#define KT   128
#define BAND 191
#define ESTR 196   // 192 + 4 pad
#define ATTN_SMEM_FLOATS (2*64*68 + 64*132 + 128*68 + 2*64*196 + 4*64 + 64*16)
#define ATTN_SMEM_BYTES  (ATTN_SMEM_FLOATS * 4)

__global__ __launch_bounds__(256, 1)
void attn_kernel(const float* __restrict__ gq, const float* __restrict__ gk,
                 const float* __restrict__ gv, const float* __restrict__ gE,
                 const float* __restrict__ ub, const float* __restrict__ vb,
                 float* __restrict__ gatt) {
    extern __shared__ float sm[];
    float* sQuT = sm;                 // [64 d][68]
    float* sQvT = sQuT + 64*68;       // [64 d][68]
    float* sKT  = sQvT + 64*68;       // [64 d][132]
    float* sV   = sKT  + 64*132;      // [128 kj][68]
    float* sEt  = sV   + 128*68;      // [64 d][196]
    float* sT2  = sEt  + 64*196;      // [64 qi][196]; sP aliases (stride 132)
    float* sP   = sT2;
    float* m_run    = sT2 + 64*196;
    float* l_run    = m_run + 64;
    float* rowscale = l_run + 64;
    float* msub     = rowscale + 64;
    float* red      = msub + 64;      // [64][16]

    const int tid = threadIdx.x;
    const int tx  = tid & 15;
    const int ty  = tid >> 4;
    const int b   = blockIdx.y >> 3;
    const int h   = blockIdx.y & 7;
    const int q0  = blockIdx.x * 64;
    const size_t headoff = (size_t)h * DHD;

    #pragma unroll
    for (int it = 0; it < 4; it++) {
        int idx = tid + it*256;
        int row = idx >> 4;
        int c4  = (idx & 15) * 4;
        float4 val = *(const float4*)(gq + ((size_t)(b*SEQ) + q0 + row)*DIM + headoff + c4);
        float4 u4  = *(const float4*)(ub + headoff + c4);
        float4 v4  = *(const float4*)(vb + headoff + c4);
        sQuT[(c4+0)*68+row] = val.x + u4.x;
        sQuT[(c4+1)*68+row] = val.y + u4.y;
        sQuT[(c4+2)*68+row] = val.z + u4.z;
        sQuT[(c4+3)*68+row] = val.w + u4.w;
        sQvT[(c4+0)*68+row] = val.x + v4.x;
        sQvT[(c4+1)*68+row] = val.y + v4.y;
        sQvT[(c4+2)*68+row] = val.z + v4.z;
        sQvT[(c4+3)*68+row] = val.w + v4.w;
    }
    if (tid < 64) { m_run[tid] = -INFINITY; l_run[tid] = 0.f; }
    float accO[4][4];
    #pragma unroll
    for (int i = 0; i < 4; i++)
        #pragma unroll
        for (int j = 0; j < 4; j++) accO[i][j] = 0.f;
    __syncthreads();

    for (int kt = 0; kt < 8; kt++) {
        const int k0 = kt * KT;
        #pragma unroll
        for (int it = 0; it < 8; it++) {
            int idx = tid + it*256;
            int row = idx >> 4;
            int c4  = (idx & 15) * 4;
            float4 kvv = *(const float4*)(gk + ((size_t)(b*SEQ) + k0 + row)*DIM + headoff + c4);
            sKT[(c4+0)*132+row] = kvv.x; sKT[(c4+1)*132+row] = kvv.y;
            sKT[(c4+2)*132+row] = kvv.z; sKT[(c4+3)*132+row] = kvv.w;
            float4 vvv = *(const float4*)(gv + ((size_t)(b*SEQ) + k0 + row)*DIM + headoff + c4);
            *(float4*)&sV[row*68 + c4] = vvv;
        }
        const int rbase = k0 - q0 + (SEQ - 64);
        #pragma unroll
        for (int it = 0; it < 12; it++) {
            int idx  = tid + it*256;
            int trow = idx >> 4;
            int c4   = (idx & 15) * 4;
            float4 ev = make_float4(0.f, 0.f, 0.f, 0.f);
            if (trow < BAND)
                ev = *(const float4*)(gE + (size_t)(rbase + trow)*DIM + headoff + c4);
            sEt[(c4+0)*ESTR+trow] = ev.x; sEt[(c4+1)*ESTR+trow] = ev.y;
            sEt[(c4+2)*ESTR+trow] = ev.z; sEt[(c4+3)*ESTR+trow] = ev.w;
        }
        __syncthreads();

        {
            float acc2[4][12];
            #pragma unroll
            for (int i = 0; i < 4; i++)
                #pragma unroll
                for (int j = 0; j < 12; j++) acc2[i][j] = 0.f;
            #pragma unroll 4
            for (int d = 0; d < 64; d++) {
                float a[4], e[12];
                *(float4*)a     = *(float4*)&sQvT[d*68 + ty*4];
                *(float4*)(e)   = *(float4*)&sEt[d*ESTR + tx*12];
                *(float4*)(e+4) = *(float4*)&sEt[d*ESTR + tx*12 + 4];
                *(float4*)(e+8) = *(float4*)&sEt[d*ESTR + tx*12 + 8];
                #pragma unroll
                for (int i = 0; i < 4; i++)
                    #pragma unroll
                    for (int j = 0; j < 12; j++)
                        acc2[i][j] += a[i] * e[j];
            }
            #pragma unroll
            for (int i = 0; i < 4; i++) {
                *(float4*)&sT2[(ty*4+i)*ESTR + tx*12]     = *(float4*)&acc2[i][0];
                *(float4*)&sT2[(ty*4+i)*ESTR + tx*12 + 4] = *(float4*)&acc2[i][4];
                *(float4*)&sT2[(ty*4+i)*ESTR + tx*12 + 8] = *(float4*)&acc2[i][8];
            }
        }
        __syncthreads();

        float S[4][8];
        {
            float acc1[4][8];
            #pragma unroll
            for (int i = 0; i < 4; i++)
                #pragma unroll
                for (int j = 0; j < 8; j++) acc1[i][j] = 0.f;
            #pragma unroll 8
            for (int d = 0; d < 64; d++) {
                float a[4], kk_[8];
                *(float4*)a        = *(float4*)&sQuT[d*68 + ty*4];
                *(float4*)(kk_)    = *(float4*)&sKT[d*132 + tx*8];
                *(float4*)(kk_+4)  = *(float4*)&sKT[d*132 + tx*8 + 4];
                #pragma unroll
                for (int i = 0; i < 4; i++)
                    #pragma unroll
                    for (int j = 0; j < 8; j++)
                        acc1[i][j] += a[i] * kk_[j];
            }
            #pragma unroll
            for (int i = 0; i < 4; i++)
                #pragma unroll
                for (int j = 0; j < 8; j++) {
                    int t = (tx*8 + j) - (ty*4 + i) + 63;
                    S[i][j] = (acc1[i][j] + sT2[(ty*4+i)*ESTR + t]) * 0.125f;
                }
        }

        #pragma unroll
        for (int i = 0; i < 4; i++) {
            float pm = S[i][0];
            #pragma unroll
            for (int j = 1; j < 8; j++) pm = fmaxf(pm, S[i][j]);
            red[(ty*4+i)*16 + tx] = pm;
        }
        __syncthreads();
        if (tid < 64) {
            float tm = red[tid*16];
            #pragma unroll
            for (int c2 = 1; c2 < 16; c2++) tm = fmaxf(tm, red[tid*16 + c2]);
            float mold = m_run[tid];
            float mn   = fmaxf(mold, tm);
            float rs   = (mold == -INFINITY) ? 0.f : __expf(mold - mn);
            rowscale[tid] = rs;
            msub[tid]     = mn;
            m_run[tid]    = mn;
            l_run[tid]   *= rs;
        }
        __syncthreads();
        #pragma unroll
        for (int i = 0; i < 4; i++) {
            int row  = ty*4 + i;
            float mn = msub[row];
            float rs = rowscale[row];
            float ps = 0.f;
            float pv[8];
            #pragma unroll
            for (int j = 0; j < 8; j++) {
                float p = __expf(S[i][j] - mn);
                pv[j] = p;
                ps += p;
            }
            *(float4*)&sP[row*132 + tx*8]     = *(float4*)&pv[0];
            *(float4*)&sP[row*132 + tx*8 + 4] = *(float4*)&pv[4];
            #pragma unroll
            for (int j = 0; j < 4; j++) accO[i][j] *= rs;
            red[row*16 + tx] = ps;
        }
        __syncthreads();
        if (tid < 64) {
            float ssum = 0.f;
            #pragma unroll
            for (int c2 = 0; c2 < 16; c2++) ssum += red[tid*16 + c2];
            l_run[tid] += ssum;
        }

        #pragma unroll 8
        for (int kj = 0; kj < KT; kj++) {
            float vv[4];
            *(float4*)vv = *(float4*)&sV[kj*68 + tx*4];
            #pragma unroll
            for (int i = 0; i < 4; i++) {
                float p = sP[(ty*4+i)*132 + kj];
                #pragma unroll
                for (int j = 0; j < 4; j++)
                    accO[i][j] += p * vv[j];
            }
        }
        __syncthreads();
    }

    #pragma unroll
    for (int i = 0; i < 4; i++) {
        int row = ty*4 + i;
        float inv = 1.f / l_run[row];
        float4 o;
        o.x = accO[i][0]*inv; o.y = accO[i][1]*inv;
        o.z = accO[i][2]*inv; o.w = accO[i][3]*inv;
        *(float4*)(gatt + ((size_t)(b*SEQ) + q0 + row)*DIM + headoff + tx*4) = o;
    }
}

// ---------------- launcher ----------------
extern "C" void kernel_launch(void* const* d_in, const int* in_sizes, int n_in,
                              void* d_out, int out_size) {
    const float* query  = (const float*)d_in[0];
    const float* key_   = (const float*)d_in[1];
    const float* value  = (const float*)d_in[2];
    const float* Wq     = (const float*)d_in[3];
    const float* bq     = (const float*)d_in[4];
    const float* Wk     = (const float*)d_in[5];
    const float* bk     = (const float*)d_in[6];
    const float* Wv     = (const float*)d_in[7];
    const float* bv     = (const float*)d_in[8];
    const float* Wp     = (const float*)d_in[9];
    const float* bp     = (const float*)d_in[10];
    const float* Wo     = (const float*)d_in[11];
    const float* bo     = (const float*)d_in[12];
    const float* u_bias = (const float*)d_in[13];
    const float* v_bias = (const float*)d_in[14];
    float* out = (float*)d_out;

    float *pq, *pk, *pv, *ppe, *pE, *patt;
    cudaGetSymbolAddress((void**)&pq,   g_q);
    cudaGetSymbolAddress((void**)&pk,   g_k);
    cudaGetSymbolAddress((void**)&pv,   g_v);
    cudaGetSymbolAddress((void**)&ppe,  g_pe);
    cudaGetSymbolAddress((void**)&pE,   g_E);
    cudaGetSymbolAddress((void**)&patt, g_att);

    cudaFuncSetAttribute(attn_kernel, cudaFuncAttributeMaxDynamicSharedMemorySize,
                         ATTN_SMEM_BYTES);

    pe_kernel<<<R2, 256>>>(ppe);
    proj_fused<<<dim3(4, 32, 4), 256>>>(query, key_, value, ppe,
                                        Wq, bq, Wk, bk, Wv, bv, Wp, bp,
                                        pq, pk, pv, pE);
    attn_kernel<<<dim3(16, 32), 256, ATTN_SMEM_BYTES>>>(pq, pk, pv, pE,
                                                        u_bias, v_bias, patt);
    gemm_tf32<<<dim3(4, 32), 256>>>(patt, Wo, bo, out, BATCH*SEQ);
}

// round 5
// speedup vs baseline: 2.7666x; 2.7666x over previous
#include <cuda_runtime.h>
#include <math.h>
#include <stdint.h>

#define BATCH 4
#define SEQ   1024
#define DIM   512
#define NH    8
#define DHD   64
#define R2    2047   // 2*SEQ-1

// ---------------- scratch (static device memory; no allocs) ----------------
__device__ float g_q[BATCH*SEQ*DIM];
__device__ float g_k[BATCH*SEQ*DIM];
__device__ float g_v[BATCH*SEQ*DIM];
__device__ float g_pe[R2*DIM];
__device__ float g_E[R2*DIM];
__device__ float g_att[BATCH*SEQ*DIM];

// ---------------- relative sinusoidal PE (all-float) ----------------------
__global__ void pe_kernel(float* __restrict__ pe) {
    int i = blockIdx.x;           // 0..2046
    int j = threadIdx.x;          // 0..255
    float pos  = (float)(SEQ - 1 - i);
    float invf = expf(-(float)j * 0.03597789207803197f);   // ln(1e4)/256
    float ang  = pos * invf;
    float s, c;
    sincosf(ang, &s, &c);
    pe[(size_t)i*DIM + 2*j]     = s;
    pe[(size_t)i*DIM + 2*j + 1] = c;
}

// ---------------- tf32 helpers --------------------------------------------
__device__ __forceinline__ float f2tf_f(float x) {
    uint32_t r;
    asm("cvt.rna.tf32.f32 %0, %1;" : "=r"(r) : "f"(x));
    return __uint_as_float(r);
}

__device__ __forceinline__ void mma_tf32(float c[4], float a0, float a1,
                                         float a2, float a3,
                                         float b0, float b1) {
    uint32_t ua0 = __float_as_uint(a0), ua1 = __float_as_uint(a1);
    uint32_t ua2 = __float_as_uint(a2), ua3 = __float_as_uint(a3);
    uint32_t ub0 = __float_as_uint(b0), ub1 = __float_as_uint(b1);
    asm volatile(
        "mma.sync.aligned.m16n8k8.row.col.f32.tf32.tf32.f32 "
        "{%0,%1,%2,%3}, {%4,%5,%6,%7}, {%8,%9}, {%0,%1,%2,%3};"
        : "+f"(c[0]), "+f"(c[1]), "+f"(c[2]), "+f"(c[3])
        : "r"(ua0), "r"(ua1), "r"(ua2), "r"(ua3), "r"(ub0), "r"(ub1));
}

// ---------------- single-tf32 GEMM: C = A @ W^T + bias --------------------
// 128x128 tile, K-chunk 16, 8 warps (2x4), warp tile 64x32.
// Operands stored row-major [m][k]/[n][k] pitch 20 -> conflict-free frags.
#define GPITCH 20

__device__ __forceinline__
void gemm_tf32_body(const float* __restrict__ A, const float* __restrict__ W,
                    const float* __restrict__ bias, float* __restrict__ C, int M) {
    __shared__ float sA[128*GPITCH];
    __shared__ float sW[128*GPITCH];

    const int tid  = threadIdx.x;
    const int lane = tid & 31;
    const int warp = tid >> 5;
    const int r    = lane >> 2;       // 0..7
    const int cg   = lane & 3;        // 0..3
    const int m0w  = (warp >> 2) * 64;
    const int n0w  = (warp & 3) * 32;
    const int m0   = blockIdx.y * 128;
    const int n0   = blockIdx.x * 128;

    float acc[4][4][4];
    #pragma unroll
    for (int mt = 0; mt < 4; mt++)
        #pragma unroll
        for (int nt = 0; nt < 4; nt++)
            #pragma unroll
            for (int e = 0; e < 4; e++) acc[mt][nt][e] = 0.f;

    for (int k0 = 0; k0 < DIM; k0 += 16) {
        #pragma unroll
        for (int it = 0; it < 2; it++) {
            int idx = tid + it*256;
            int row = idx >> 2;            // 0..127
            int lc  = (idx & 3) * 4;       // 0,4,8,12
            int m   = m0 + row;
            float4 va = make_float4(0.f, 0.f, 0.f, 0.f);
            if (m < M) va = *(const float4*)(A + (size_t)m*DIM + k0 + lc);
            float4 ca;
            ca.x = f2tf_f(va.x); ca.y = f2tf_f(va.y);
            ca.z = f2tf_f(va.z); ca.w = f2tf_f(va.w);
            *(float4*)&sA[row*GPITCH + lc] = ca;
            float4 vb = *(const float4*)(W + (size_t)(n0+row)*DIM + k0 + lc);
            float4 cb;
            cb.x = f2tf_f(vb.x); cb.y = f2tf_f(vb.y);
            cb.z = f2tf_f(vb.z); cb.w = f2tf_f(vb.w);
            *(float4*)&sW[row*GPITCH + lc] = cb;
        }
        __syncthreads();

        #pragma unroll
        for (int ks = 0; ks < 16; ks += 8) {
            float a[4][4];
            #pragma unroll
            for (int mt = 0; mt < 4; mt++) {
                int mrow = m0w + mt*16 + r;
                a[mt][0] = sA[mrow*GPITCH     + ks + cg];
                a[mt][1] = sA[(mrow+8)*GPITCH + ks + cg];
                a[mt][2] = sA[mrow*GPITCH     + ks + cg + 4];
                a[mt][3] = sA[(mrow+8)*GPITCH + ks + cg + 4];
            }
            #pragma unroll
            for (int nt = 0; nt < 4; nt++) {
                int nrow = n0w + nt*8 + r;
                float b0 = sW[nrow*GPITCH + ks + cg];
                float b1 = sW[nrow*GPITCH + ks + cg + 4];
                #pragma unroll
                for (int mt = 0; mt < 4; mt++)
                    mma_tf32(acc[mt][nt], a[mt][0], a[mt][1], a[mt][2], a[mt][3], b0, b1);
            }
        }
        __syncthreads();
    }

    #pragma unroll
    for (int mt = 0; mt < 4; mt++) {
        int m = m0 + m0w + mt*16 + r;
        #pragma unroll
        for (int nt = 0; nt < 4; nt++) {
            int n = n0 + n0w + nt*8 + 2*cg;
            float2 bb = *(const float2*)(bias + n);
            if (m < M) {
                float2 o0 = make_float2(acc[mt][nt][0] + bb.x, acc[mt][nt][1] + bb.y);
                *(float2*)(C + (size_t)m*DIM + n) = o0;
            }
            if (m + 8 < M) {
                float2 o1 = make_float2(acc[mt][nt][2] + bb.x, acc[mt][nt][3] + bb.y);
                *(float2*)(C + (size_t)(m+8)*DIM + n) = o1;
            }
        }
    }
}

__global__ __launch_bounds__(256, 2)
void proj_fused(const float* __restrict__ q_in, const float* __restrict__ k_in,
                const float* __restrict__ v_in, const float* __restrict__ pe_in,
                const float* __restrict__ Wq, const float* __restrict__ bq,
                const float* __restrict__ Wk, const float* __restrict__ bk,
                const float* __restrict__ Wv, const float* __restrict__ bv,
                const float* __restrict__ Wp, const float* __restrict__ bp,
                float* __restrict__ oq, float* __restrict__ ok,
                float* __restrict__ ov, float* __restrict__ oE) {
    int z = blockIdx.z;
    const float *A, *W, *b; float* C; int M;
    if (z == 0)      { A = q_in;  W = Wq; b = bq; C = oq; M = BATCH*SEQ; }
    else if (z == 1) { A = k_in;  W = Wk; b = bk; C = ok; M = BATCH*SEQ; }
    else if (z == 2) { A = v_in;  W = Wv; b = bv; C = ov; M = BATCH*SEQ; }
    else             { A = pe_in; W = Wp; b = bp; C = oE; M = R2;
                       if (blockIdx.y >= 16) return; }
    gemm_tf32_body(A, W, b, C, M);
}

__global__ __launch_bounds__(256, 2)
void gemm_tf32(const float* __restrict__ A, const float* __restrict__ W,
               const float* __restrict__ bias, float* __restrict__ C, int M) {
    gemm_tf32_body(A, W, bias, C, M);
}

// ---------------- tensor-core rel-pos flash attention ---------------------
// Block = (b,h, 64-row q-tile). 8 k-tiles of 128. 8 warps.
// T2[64x192] = Qv @ Eband^T ; S[64x128] = Qu@K^T + shift(T2) ; O += P@V.
#define PA   68    // pitch: sQu,sQv,sK,sE  (row-major [m|n][k=64])
#define PVP  72    // sV pitch ([kj][d])
#define PT2  196   // sT2 [qi][t]
#define PP   132   // sP  [qi][kj]
#define ATTN_SMEM_FLOATS (64*PA*2 + 128*PA + 128*PVP + 192*PA + 64*PT2 + 4*64 + 64*8)
#define ATTN_SMEM_BYTES  (ATTN_SMEM_FLOATS * 4)

__global__ __launch_bounds__(256, 1)
void attn_tc(const float* __restrict__ gq, const float* __restrict__ gk,
             const float* __restrict__ gv, const float* __restrict__ gE,
             const float* __restrict__ ub, const float* __restrict__ vb,
             float* __restrict__ gatt) {
    extern __shared__ float sm[];
    float* sQu = sm;                      // [64][68]
    float* sQv = sQu + 64*PA;             // [64][68]
    float* sK  = sQv + 64*PA;             // [128][68]
    float* sV  = sK  + 128*PA;            // [128][72]
    float* sE  = sV  + 128*PVP;           // [192][68]
    float* sT2 = sE  + 192*PA;            // [64][196]
    float* sP  = sT2;                     // alias: [64][132], T2 dead by then
    float* m_run    = sT2 + 64*PT2;       // [64]
    float* l_run    = m_run + 64;
    float* rowscale = l_run + 64;
    float* msub     = rowscale + 64;
    float* red      = msub + 64;          // [64][8]

    const int tid  = threadIdx.x;
    const int w    = tid >> 5;
    const int lane = tid & 31;
    const int r    = lane >> 2;           // 0..7
    const int cg   = lane & 3;            // 0..3
    const int b    = blockIdx.y >> 3;
    const int h    = blockIdx.y & 7;
    const int q0   = blockIdx.x * 64;
    const size_t base_bh = (size_t)(b*SEQ)*DIM + (size_t)h*DHD;

    // ---- load Qu/Qv (row-major, bias fused, tf32-rounded) ----
    #pragma unroll
    for (int it = 0; it < 4; it++) {
        int idx = tid + it*256;
        int row = idx >> 4;               // 0..63
        int c4  = (idx & 15) * 4;
        float4 val = *(const float4*)(gq + base_bh + (size_t)(q0+row)*DIM + c4);
        float4 u4  = *(const float4*)(ub + h*DHD + c4);
        float4 v4  = *(const float4*)(vb + h*DHD + c4);
        float4 ou, ov_;
        ou.x  = f2tf_f(val.x + u4.x); ou.y  = f2tf_f(val.y + u4.y);
        ou.z  = f2tf_f(val.z + u4.z); ou.w  = f2tf_f(val.w + u4.w);
        ov_.x = f2tf_f(val.x + v4.x); ov_.y = f2tf_f(val.y + v4.y);
        ov_.z = f2tf_f(val.z + v4.z); ov_.w = f2tf_f(val.w + v4.w);
        *(float4*)&sQu[row*PA + c4] = ou;
        *(float4*)&sQv[row*PA + c4] = ov_;
    }
    if (tid < 64) { m_run[tid] = -INFINITY; l_run[tid] = 0.f; }
    float accO[4][4];
    #pragma unroll
    for (int mt = 0; mt < 4; mt++)
        #pragma unroll
        for (int e = 0; e < 4; e++) accO[mt][e] = 0.f;
    __syncthreads();

    for (int kt = 0; kt < 8; kt++) {
        const int k0 = kt * 128;
        // ---- load K, V (row-major, tf32) ----
        #pragma unroll
        for (int it = 0; it < 8; it++) {
            int idx = tid + it*256;
            int row = idx >> 4;           // 0..127
            int c4  = (idx & 15) * 4;
            float4 kv = *(const float4*)(gk + base_bh + (size_t)(k0+row)*DIM + c4);
            float4 ck;
            ck.x = f2tf_f(kv.x); ck.y = f2tf_f(kv.y);
            ck.z = f2tf_f(kv.z); ck.w = f2tf_f(kv.w);
            *(float4*)&sK[row*PA + c4] = ck;
            float4 vv = *(const float4*)(gv + base_bh + (size_t)(k0+row)*DIM + c4);
            float4 cv;
            cv.x = f2tf_f(vv.x); cv.y = f2tf_f(vv.y);
            cv.z = f2tf_f(vv.z); cv.w = f2tf_f(vv.w);
            *(float4*)&sV[row*PVP + c4] = cv;
        }
        // ---- load E band rows [rbase, rbase+190] (row-major, tf32) ----
        const int rbase = k0 - q0 + (SEQ - 64);
        #pragma unroll
        for (int it = 0; it < 12; it++) {
            int idx  = tid + it*256;
            int trow = idx >> 4;          // 0..191
            int c4   = (idx & 15) * 4;
            float4 ev = make_float4(0.f, 0.f, 0.f, 0.f);
            if (trow < 191)
                ev = *(const float4*)(gE + (size_t)(rbase + trow)*DIM + h*DHD + c4);
            float4 ce;
            ce.x = f2tf_f(ev.x); ce.y = f2tf_f(ev.y);
            ce.z = f2tf_f(ev.z); ce.w = f2tf_f(ev.w);
            *(float4*)&sE[trow*PA + c4] = ce;
        }
        __syncthreads();

        // ---- T2 = Qv @ Eband^T : warp w covers t in [24w, 24w+24) ----
        {
            float accT[4][3][4];
            #pragma unroll
            for (int mt = 0; mt < 4; mt++)
                #pragma unroll
                for (int nt = 0; nt < 3; nt++)
                    #pragma unroll
                    for (int e = 0; e < 4; e++) accT[mt][nt][e] = 0.f;
            #pragma unroll
            for (int ks = 0; ks < 64; ks += 8) {
                float a[4][4];
                #pragma unroll
                for (int mt = 0; mt < 4; mt++) {
                    int mrow = mt*16 + r;
                    a[mt][0] = sQv[mrow*PA     + ks + cg];
                    a[mt][1] = sQv[(mrow+8)*PA + ks + cg];
                    a[mt][2] = sQv[mrow*PA     + ks + cg + 4];
                    a[mt][3] = sQv[(mrow+8)*PA + ks + cg + 4];
                }
                #pragma unroll
                for (int nt = 0; nt < 3; nt++) {
                    int tn = w*24 + nt*8 + r;
                    float b0 = sE[tn*PA + ks + cg];
                    float b1 = sE[tn*PA + ks + cg + 4];
                    #pragma unroll
                    for (int mt = 0; mt < 4; mt++)
                        mma_tf32(accT[mt][nt], a[mt][0], a[mt][1], a[mt][2], a[mt][3], b0, b1);
                }
            }
            #pragma unroll
            for (int mt = 0; mt < 4; mt++) {
                int row  = mt*16 + r;
                #pragma unroll
                for (int nt = 0; nt < 3; nt++) {
                    int tcol = w*24 + nt*8 + 2*cg;
                    *(float2*)&sT2[row*PT2 + tcol]     = make_float2(accT[mt][nt][0], accT[mt][nt][1]);
                    *(float2*)&sT2[(row+8)*PT2 + tcol] = make_float2(accT[mt][nt][2], accT[mt][nt][3]);
                }
            }
        }
        __syncthreads();

        // ---- S = Qu @ K^T + shift(T2), scaled : warp w covers kj [16w,16w+16) ----
        float sv[4][2][4];
        {
            #pragma unroll
            for (int mt = 0; mt < 4; mt++)
                #pragma unroll
                for (int nt = 0; nt < 2; nt++)
                    #pragma unroll
                    for (int e = 0; e < 4; e++) sv[mt][nt][e] = 0.f;
            #pragma unroll
            for (int ks = 0; ks < 64; ks += 8) {
                float a[4][4];
                #pragma unroll
                for (int mt = 0; mt < 4; mt++) {
                    int mrow = mt*16 + r;
                    a[mt][0] = sQu[mrow*PA     + ks + cg];
                    a[mt][1] = sQu[(mrow+8)*PA + ks + cg];
                    a[mt][2] = sQu[mrow*PA     + ks + cg + 4];
                    a[mt][3] = sQu[(mrow+8)*PA + ks + cg + 4];
                }
                #pragma unroll
                for (int nt = 0; nt < 2; nt++) {
                    int kn = w*16 + nt*8 + r;
                    float b0 = sK[kn*PA + ks + cg];
                    float b1 = sK[kn*PA + ks + cg + 4];
                    #pragma unroll
                    for (int mt = 0; mt < 4; mt++)
                        mma_tf32(sv[mt][nt], a[mt][0], a[mt][1], a[mt][2], a[mt][3], b0, b1);
                }
            }
            #pragma unroll
            for (int mt = 0; mt < 4; mt++) {
                int rowA = mt*16 + r;
                #pragma unroll
                for (int nt = 0; nt < 2; nt++) {
                    int kj = w*16 + nt*8 + 2*cg;
                    int tA = kj - rowA + 63;          // 0..190
                    int tB = tA - 8;
                    sv[mt][nt][0] = (sv[mt][nt][0] + sT2[rowA*PT2 + tA])       * 0.125f;
                    sv[mt][nt][1] = (sv[mt][nt][1] + sT2[rowA*PT2 + tA + 1])   * 0.125f;
                    sv[mt][nt][2] = (sv[mt][nt][2] + sT2[(rowA+8)*PT2 + tB])   * 0.125f;
                    sv[mt][nt][3] = (sv[mt][nt][3] + sT2[(rowA+8)*PT2 + tB+1]) * 0.125f;
                }
            }
        }

        // ---- online softmax: row max across warps ----
        #pragma unroll
        for (int mt = 0; mt < 4; mt++) {
            float mA = fmaxf(fmaxf(sv[mt][0][0], sv[mt][0][1]), fmaxf(sv[mt][1][0], sv[mt][1][1]));
            float mB = fmaxf(fmaxf(sv[mt][0][2], sv[mt][0][3]), fmaxf(sv[mt][1][2], sv[mt][1][3]));
            mA = fmaxf(mA, __shfl_xor_sync(0xffffffffu, mA, 1));
            mA = fmaxf(mA, __shfl_xor_sync(0xffffffffu, mA, 2));
            mB = fmaxf(mB, __shfl_xor_sync(0xffffffffu, mB, 1));
            mB = fmaxf(mB, __shfl_xor_sync(0xffffffffu, mB, 2));
            if (cg == 0) {
                red[(mt*16 + r)*8 + w]     = mA;
                red[(mt*16 + r + 8)*8 + w] = mB;
            }
        }
        __syncthreads();
        if (tid < 64) {
            float tm = red[tid*8];
            #pragma unroll
            for (int c2 = 1; c2 < 8; c2++) tm = fmaxf(tm, red[tid*8 + c2]);
            float mold = m_run[tid];
            float mn   = fmaxf(mold, tm);
            float rs   = (mold == -INFINITY) ? 0.f : __expf(mold - mn);
            rowscale[tid] = rs;
            msub[tid]     = mn;
            m_run[tid]    = mn;
            l_run[tid]   *= rs;
        }
        __syncthreads();

        // ---- p = exp(S - m), write P (tf32) row-major, partial sums, rescale O ----
        #pragma unroll
        for (int mt = 0; mt < 4; mt++) {
            int rowA = mt*16 + r;
            int rowB = rowA + 8;
            float mnA = msub[rowA], mnB = msub[rowB];
            float sumA = 0.f, sumB = 0.f;
            #pragma unroll
            for (int nt = 0; nt < 2; nt++) {
                int kj = w*16 + nt*8 + 2*cg;
                float p0 = __expf(sv[mt][nt][0] - mnA);
                float p1 = __expf(sv[mt][nt][1] - mnA);
                float p2 = __expf(sv[mt][nt][2] - mnB);
                float p3 = __expf(sv[mt][nt][3] - mnB);
                sumA += p0 + p1;
                sumB += p2 + p3;
                *(float2*)&sP[rowA*PP + kj] = make_float2(f2tf_f(p0), f2tf_f(p1));
                *(float2*)&sP[rowB*PP + kj] = make_float2(f2tf_f(p2), f2tf_f(p3));
            }
            sumA += __shfl_xor_sync(0xffffffffu, sumA, 1);
            sumA += __shfl_xor_sync(0xffffffffu, sumA, 2);
            sumB += __shfl_xor_sync(0xffffffffu, sumB, 1);
            sumB += __shfl_xor_sync(0xffffffffu, sumB, 2);
            if (cg == 0) {
                red[rowA*8 + w] = sumA;
                red[rowB*8 + w] = sumB;
            }
            float rsA = rowscale[rowA], rsB = rowscale[rowB];
            accO[mt][0] *= rsA; accO[mt][1] *= rsA;
            accO[mt][2] *= rsB; accO[mt][3] *= rsB;
        }
        __syncthreads();
        if (tid < 64) {
            float ssum = 0.f;
            #pragma unroll
            for (int c2 = 0; c2 < 8; c2++) ssum += red[tid*8 + c2];
            l_run[tid] += ssum;
        }

        // ---- O += P @ V : warp w covers d-cols [8w, 8w+8) ----
        #pragma unroll
        for (int ks = 0; ks < 128; ks += 8) {
            float a[4][4];
            #pragma unroll
            for (int mt = 0; mt < 4; mt++) {
                int mrow = mt*16 + r;
                a[mt][0] = sP[mrow*PP     + ks + cg];
                a[mt][1] = sP[(mrow+8)*PP + ks + cg];
                a[mt][2] = sP[mrow*PP     + ks + cg + 4];
                a[mt][3] = sP[(mrow+8)*PP + ks + cg + 4];
            }
            float b0 = sV[(ks+cg)*PVP   + w*8 + r];
            float b1 = sV[(ks+cg+4)*PVP + w*8 + r];
            #pragma unroll
            for (int mt = 0; mt < 4; mt++)
                mma_tf32(accO[mt], a[mt][0], a[mt][1], a[mt][2], a[mt][3], b0, b1);
        }
        __syncthreads();
    }

    // ---- normalize + store ----
    #pragma unroll
    for (int mt = 0; mt < 4; mt++) {
        int rowA = mt*16 + r;
        int rowB = rowA + 8;
        float invA = 1.f / l_run[rowA];
        float invB = 1.f / l_run[rowB];
        int col = w*8 + 2*cg;
        float2 o0 = make_float2(accO[mt][0]*invA, accO[mt][1]*invA);
        float2 o1 = make_float2(accO[mt][2]*invB, accO[mt][3]*invB);
        *(float2*)(gatt + base_bh + (size_t)(q0 + rowA)*DIM + col) = o0;
        *(float2*)(gatt + base_bh + (size_t)(q0 + rowB)*DIM + col) = o1;
    }
}

// ---------------- launcher ----------------
extern "C" void kernel_launch(void* const* d_in, const int* in_sizes, int n_in,
                              void* d_out, int out_size) {
    const float* query  = (const float*)d_in[0];
    const float* key_   = (const float*)d_in[1];
    const float* value  = (const float*)d_in[2];
    const float* Wq     = (const float*)d_in[3];
    const float* bq     = (const float*)d_in[4];
    const float* Wk     = (const float*)d_in[5];
    const float* bk     = (const float*)d_in[6];
    const float* Wv     = (const float*)d_in[7];
    const float* bv     = (const float*)d_in[8];
    const float* Wp     = (const float*)d_in[9];
    const float* bp     = (const float*)d_in[10];
    const float* Wo     = (const float*)d_in[11];
    const float* bo     = (const float*)d_in[12];
    const float* u_bias = (const float*)d_in[13];
    const float* v_bias = (const float*)d_in[14];
    float* out = (float*)d_out;

    float *pq, *pk, *pv, *ppe, *pE, *patt;
    cudaGetSymbolAddress((void**)&pq,   g_q);
    cudaGetSymbolAddress((void**)&pk,   g_k);
    cudaGetSymbolAddress((void**)&pv,   g_v);
    cudaGetSymbolAddress((void**)&ppe,  g_pe);
    cudaGetSymbolAddress((void**)&pE,   g_E);
    cudaGetSymbolAddress((void**)&patt, g_att);

    cudaFuncSetAttribute(attn_tc, cudaFuncAttributeMaxDynamicSharedMemorySize,
                         ATTN_SMEM_BYTES);

    pe_kernel<<<R2, 256>>>(ppe);
    proj_fused<<<dim3(4, 32, 4), 256>>>(query, key_, value, ppe,
                                        Wq, bq, Wk, bk, Wv, bv, Wp, bp,
                                        pq, pk, pv, pE);
    attn_tc<<<dim3(16, 32), 256, ATTN_SMEM_BYTES>>>(pq, pk, pv, pE,
                                                    u_bias, v_bias, patt);
    gemm_tf32<<<dim3(4, 32), 256>>>(patt, Wo, bo, out, BATCH*SEQ);
}